// round 9
// baseline (speedup 1.0000x reference)
#include <cuda_runtime.h>
#include <cuda_bf16.h>
#include <cstdint>
#include <cstddef>

// ---------------------------------------------------------------------------
// Problem constants
// ---------------------------------------------------------------------------
#define Bdim  8
#define Fdim  16
#define Pdim  196
#define Ddim  768
#define Hh    12
#define HD    64
#define Ndim  3136              // F*P
#define Mrows 25088             // B*N
#define E3    2304              // 3*D

#define HEAD_ELEMS ((size_t)Bdim * Hh * Ndim * HD)
#define MD_ELEMS   ((size_t)Mrows * Ddim)

// Scratch (__device__ globals; allocation-free rule)
__device__ float g_q[HEAD_ELEMS];
__device__ float g_k[HEAD_ELEMS];
__device__ float g_v[HEAD_ELEMS];

__device__ __nv_bfloat16 g_xhi[MD_ELEMS];
__device__ __nv_bfloat16 g_xlo[MD_ELEMS];
__device__ __nv_bfloat16 g_wqkv_hi[(size_t)E3 * Ddim];
__device__ __nv_bfloat16 g_wqkv_lo[(size_t)E3 * Ddim];
__device__ __nv_bfloat16 g_wproj_hi[(size_t)Ddim * Ddim];
__device__ __nv_bfloat16 g_wproj_lo[(size_t)Ddim * Ddim];
__device__ __nv_bfloat16 g_wf_hi[MD_ELEMS];
__device__ __nv_bfloat16 g_wf_lo[MD_ELEMS];

// ---------------------------------------------------------------------------
// helpers
// ---------------------------------------------------------------------------
__device__ __forceinline__ void cp_async16(uint32_t dst, const void* src) {
    asm volatile("cp.async.cg.shared.global [%0], [%1], 16;"
                 :: "r"(dst), "l"(src) : "memory");
}
#define CP_COMMIT() asm volatile("cp.async.commit_group;" ::: "memory")
template <int N> __device__ __forceinline__ void cp_wait() {
    asm volatile("cp.async.wait_group %0;" :: "n"(N) : "memory");
}
__device__ __forceinline__ uint32_t smem_u32(const void* p) {
    uint32_t a;
    asm("{ .reg .u64 t; cvta.to.shared.u64 t, %1; cvt.u32.u64 %0, t; }"
        : "=r"(a) : "l"(p));
    return a;
}

__device__ __forceinline__ void mma16816(float* d,
                                         uint32_t a0, uint32_t a1, uint32_t a2, uint32_t a3,
                                         uint32_t b0, uint32_t b1) {
    asm volatile(
        "mma.sync.aligned.m16n8k16.row.col.f32.bf16.bf16.f32 "
        "{%0,%1,%2,%3}, {%4,%5,%6,%7}, {%8,%9}, {%0,%1,%2,%3};"
        : "+f"(d[0]), "+f"(d[1]), "+f"(d[2]), "+f"(d[3])
        : "r"(a0), "r"(a1), "r"(a2), "r"(a3), "r"(b0), "r"(b1));
}

__device__ __forceinline__ void ldsm4(uint32_t& r0, uint32_t& r1,
                                      uint32_t& r2, uint32_t& r3, uint32_t addr) {
    asm volatile("ldmatrix.sync.aligned.m8n8.x4.shared.b16 {%0,%1,%2,%3}, [%4];"
                 : "=r"(r0), "=r"(r1), "=r"(r2), "=r"(r3) : "r"(addr));
}

// ---------------------------------------------------------------------------
// HMMA GEMM:  C = (Ahi+Alo)[M,768] * (Bhi+Blo)[N,768]^T
// 128x128x32 CTA tile, 256 threads, warp grid 2(M)x4(N), warp tile 64x32.
// mode 0: scatter epilogue into q/k/v head layout (no bias)
// mode 1: normal C[M,Nd] + bias
// ---------------------------------------------------------------------------
#define BK       32
#define LDK      40                       // padded row length (bf16)
#define TILE_B   (128 * LDK * 2)          // 10240 bytes per matrix tile
#define STAGE_B  (4 * TILE_B)             // Ahi, Alo, Bhi, Blo = 40960
#define GSMEM    (2 * STAGE_B)            // 81920
#define OFF_AHI  0
#define OFF_ALO  TILE_B
#define OFF_BHI  (2 * TILE_B)
#define OFF_BLO  (3 * TILE_B)

__global__ __launch_bounds__(256, 2) void tgemm_k(
    const __nv_bfloat16* __restrict__ Ahi, const __nv_bfloat16* __restrict__ Alo,
    const __nv_bfloat16* __restrict__ Bhi, const __nv_bfloat16* __restrict__ Blo,
    const float* __restrict__ bias, float* __restrict__ C, int Nd, int mode,
    float* __restrict__ Qo, float* __restrict__ Ko, float* __restrict__ Vo)
{
    extern __shared__ char smem[];
    const uint32_t sb = smem_u32(smem);

    const int tid  = threadIdx.x;
    const int lane = tid & 31;
    const int wid  = tid >> 5;
    const int wm   = wid & 1;          // 0..1 : M
    const int wn   = wid >> 1;         // 0..3 : N
    const int g    = lane >> 2;        // 0..7
    const int tg   = lane & 3;         // 0..3

    const int bm = blockIdx.y * 128;
    const int bn = blockIdx.x * 128;

    // ldmatrix per-lane address components
    const int a_row = wm * 64 + (lane & 15);        // + mt*16
    const int a_kc  = (lane >> 4) * 8;              // + ks*16
    const int b_row = wn * 32 + ((lane >> 4) << 3) + (lane & 7);  // + p*16
    const int b_kc  = ((lane >> 3) & 1) * 8;        // + ks*16

    // gmem->smem loader role: 4 tiles x 64 threads, 8 granules (16B) each
    const int tile = tid >> 6;         // 0:Ahi 1:Alo 2:Bhi 3:Blo
    const int lt   = tid & 63;
    const __nv_bfloat16* src_base =
        (tile == 0) ? Ahi : (tile == 1) ? Alo : (tile == 2) ? Bhi : Blo;
    const int rowbase = (tile < 2) ? bm : bn;
    const uint32_t tile_off = tile * TILE_B;

    auto load_chunk = [&](int k0, int stage) {
        const uint32_t dbase = sb + stage * STAGE_B + tile_off;
#pragma unroll
        for (int j = 0; j < 8; j++) {
            int id  = lt + j * 64;          // 0..511
            int row = id >> 2;              // 0..127
            int gr  = id & 3;               // 16B granule within 64B row
            const void* src = src_base + (size_t)(rowbase + row) * Ddim + k0 + gr * 8;
            cp_async16(dbase + (uint32_t)(row * (LDK * 2) + gr * 16), src);
        }
        CP_COMMIT();
    };

    float acc[4][4][4];
#pragma unroll
    for (int i = 0; i < 4; i++)
#pragma unroll
        for (int j = 0; j < 4; j++)
#pragma unroll
            for (int q = 0; q < 4; q++) acc[i][j][q] = 0.f;

    load_chunk(0, 0);

    const int NCH = Ddim / BK;   // 24
    for (int c = 0; c < NCH; c++) {
        cp_wait<0>();
        __syncthreads();
        if (c + 1 < NCH) load_chunk((c + 1) * BK, (c + 1) & 1);

        const uint32_t st = sb + (c & 1) * STAGE_B;

#pragma unroll
        for (int ks = 0; ks < 2; ks++) {
            const int kcA = ks * 16 + a_kc;
            const int kcB = ks * 16 + b_kc;
            uint32_t ah[4][4], al[4][4];
#pragma unroll
            for (int mt = 0; mt < 4; mt++) {
                uint32_t addr = st + (uint32_t)(((a_row + mt * 16) * LDK + kcA) * 2);
                ldsm4(ah[mt][0], ah[mt][1], ah[mt][2], ah[mt][3], addr + OFF_AHI);
                ldsm4(al[mt][0], al[mt][1], al[mt][2], al[mt][3], addr + OFF_ALO);
            }
#pragma unroll
            for (int p = 0; p < 2; p++) {
                uint32_t baddr = st + (uint32_t)(((b_row + p * 16) * LDK + kcB) * 2);
                uint32_t bh[2][2], bl[2][2];
                ldsm4(bh[0][0], bh[0][1], bh[1][0], bh[1][1], baddr + OFF_BHI);
                ldsm4(bl[0][0], bl[0][1], bl[1][0], bl[1][1], baddr + OFF_BLO);
#pragma unroll
                for (int q = 0; q < 2; q++) {
                    const int nt = p * 2 + q;
#pragma unroll
                    for (int mt = 0; mt < 4; mt++) {
                        mma16816(acc[mt][nt], ah[mt][0], ah[mt][1], ah[mt][2], ah[mt][3],
                                 bh[q][0], bh[q][1]);
                        mma16816(acc[mt][nt], ah[mt][0], ah[mt][1], ah[mt][2], ah[mt][3],
                                 bl[q][0], bl[q][1]);
                        mma16816(acc[mt][nt], al[mt][0], al[mt][1], al[mt][2], al[mt][3],
                                 bh[q][0], bh[q][1]);
                    }
                }
            }
        }
    }

    // epilogue
    if (mode == 1) {
#pragma unroll
        for (int mt = 0; mt < 4; mt++) {
            int r0 = bm + wm * 64 + mt * 16 + g;
#pragma unroll
            for (int nt = 0; nt < 4; nt++) {
                int c0 = bn + wn * 32 + nt * 8 + tg * 2;
                float b0 = bias[c0], b1 = bias[c0 + 1];
                float2 v0 = make_float2(acc[mt][nt][0] + b0, acc[mt][nt][1] + b1);
                float2 v1 = make_float2(acc[mt][nt][2] + b0, acc[mt][nt][3] + b1);
                *(float2*)(C + (size_t)r0 * Nd + c0) = v0;
                *(float2*)(C + (size_t)(r0 + 8) * Nd + c0) = v1;
            }
        }
    } else {
        // scatter into q/k/v (B,12,N,64) head layout
#pragma unroll
        for (int nt = 0; nt < 4; nt++) {
            int c0 = bn + wn * 32 + nt * 8 + tg * 2;
            int t = c0 / Ddim;
            int rem = c0 - t * Ddim;
            int h = rem >> 6, d = rem & 63;
            float* dst = (t == 0) ? Qo : (t == 1) ? Ko : Vo;
#pragma unroll
            for (int mt = 0; mt < 4; mt++) {
                int r0 = bm + wm * 64 + mt * 16 + g;
#pragma unroll
                for (int rr = 0; rr < 2; rr++) {
                    int r = r0 + rr * 8;
                    int b = r / Ndim;
                    int n = r - b * Ndim;
                    size_t off = (((size_t)(b * Hh + h)) * Ndim + n) * HD + d;
                    float2 v = make_float2(acc[mt][nt][2 * rr], acc[mt][nt][2 * rr + 1]);
                    *(float2*)(dst + off) = v;
                }
            }
        }
    }
}

// ---------------------------------------------------------------------------
// fp32 -> bf16 hi/lo split
// ---------------------------------------------------------------------------
__global__ void cvt_split_k(const float* __restrict__ in,
                            __nv_bfloat16* __restrict__ hi,
                            __nv_bfloat16* __restrict__ lo, size_t n)
{
    size_t i = (size_t)blockIdx.x * 256 + threadIdx.x;
    if (i >= n) return;
    float v = in[i];
    __nv_bfloat16 h = __float2bfloat16(v);
    hi[i] = h;
    lo[i] = __float2bfloat16(v - __bfloat162float(h));
}

// ---------------------------------------------------------------------------
// Spatial attention, split-d: 768 groups of 196 rows (heads 0..5).
// Each query row handled by a PAIR of threads (lanes 2i, 2i+1), each owning
// 32 of the 64 dims. Partial scores combined with shfl_xor(1). 416 threads
// (392 active). Output written into g_wf_hi/lo head-interleaved + bf16 split.
// ---------------------------------------------------------------------------
#define SPAT_T 416
__global__ __launch_bounds__(SPAT_T) void attn_spatial_k()
{
    __shared__ float4 K4[64][16];
    __shared__ float4 V4[64][16];

    const int g = blockIdx.x;
    const int b = g / 96;
    const int h = (g % 96) / 16;
    const int f = g % 16;
    const size_t base = (((size_t)(b * Hh + h)) * Ndim + f * Pdim) * HD;

    const int tid  = threadIdx.x;
    const int qi   = tid >> 1;          // query row within group
    const int half = tid & 1;           // which 32-dim half
    const bool active = qi < Pdim;

    float4 q4[8], a4[8];
    float mx = -1e30f, lsum = 0.f;
    if (active) {
        const float4* qp = (const float4*)(g_q + base + (size_t)qi * HD + half * 32);
#pragma unroll
        for (int i = 0; i < 8; i++) q4[i] = qp[i];
    }
#pragma unroll
    for (int i = 0; i < 8; i++) a4[i] = make_float4(0.f, 0.f, 0.f, 0.f);

    const float scale = 0.125f;
    const int hoff = half * 8;          // float4 offset of this half

    for (int j0 = 0; j0 < Pdim; j0 += 64) {
        int cnt = Pdim - j0; if (cnt > 64) cnt = 64;
        __syncthreads();
        {
            const float4* kp = (const float4*)(g_k + base + (size_t)j0 * HD);
            const float4* vp = (const float4*)(g_v + base + (size_t)j0 * HD);
            for (int t = tid; t < cnt * 16; t += SPAT_T) {
                K4[t >> 4][t & 15] = kp[t];
                V4[t >> 4][t & 15] = vp[t];
            }
        }
        __syncthreads();
        // ALL threads run the loop (inactive ones compute garbage) so that
        // every warp lane participates in the shfl. Pairs (2i,2i+1) are
        // either both active or both inactive, so garbage never leaks.
        for (int j = 0; j < cnt; j++) {
            float s0 = 0.f, s1 = 0.f;
#pragma unroll
            for (int i = 0; i < 4; i++) {
                float4 kv0 = K4[j][hoff + i];
                float4 kv1 = K4[j][hoff + 4 + i];
                s0 = fmaf(q4[i].x, kv0.x, s0);
                s0 = fmaf(q4[i].y, kv0.y, s0);
                s0 = fmaf(q4[i].z, kv0.z, s0);
                s0 = fmaf(q4[i].w, kv0.w, s0);
                s1 = fmaf(q4[4 + i].x, kv1.x, s1);
                s1 = fmaf(q4[4 + i].y, kv1.y, s1);
                s1 = fmaf(q4[4 + i].z, kv1.z, s1);
                s1 = fmaf(q4[4 + i].w, kv1.w, s1);
            }
            float sp = s0 + s1;
            sp += __shfl_xor_sync(0xFFFFFFFFu, sp, 1);
            float s = sp * scale;
            if (s <= mx) {
                float p = __expf(s - mx);
                lsum += p;
#pragma unroll
                for (int i = 0; i < 8; i++) {
                    float4 vv = V4[j][hoff + i];
                    a4[i].x = fmaf(p, vv.x, a4[i].x);
                    a4[i].y = fmaf(p, vv.y, a4[i].y);
                    a4[i].z = fmaf(p, vv.z, a4[i].z);
                    a4[i].w = fmaf(p, vv.w, a4[i].w);
                }
            } else {
                float corr = __expf(mx - s);
                lsum = lsum * corr + 1.f;
#pragma unroll
                for (int i = 0; i < 8; i++) {
                    float4 vv = V4[j][hoff + i];
                    a4[i].x = fmaf(a4[i].x, corr, vv.x);
                    a4[i].y = fmaf(a4[i].y, corr, vv.y);
                    a4[i].z = fmaf(a4[i].z, corr, vv.z);
                    a4[i].w = fmaf(a4[i].w, corr, vv.w);
                }
                mx = s;
            }
        }
    }

    if (active) {
        float inv = 1.f / lsum;
        const int nglob = f * Pdim + qi;
        const size_t obase = ((size_t)b * Ndim + nglob) * Ddim + h * HD + half * 32;
#pragma unroll
        for (int i = 0; i < 8; i++) {
            float vals[4] = { a4[i].x * inv, a4[i].y * inv, a4[i].z * inv, a4[i].w * inv };
#pragma unroll
            for (int j = 0; j < 4; j += 2) {
                float v0 = vals[j], v1 = vals[j + 1];
                __nv_bfloat16 h0 = __float2bfloat16(v0);
                __nv_bfloat16 h1 = __float2bfloat16(v1);
                __nv_bfloat162 hv; hv.x = h0; hv.y = h1;
                __nv_bfloat162 lv;
                lv.x = __float2bfloat16(v0 - __bfloat162float(h0));
                lv.y = __float2bfloat16(v1 - __bfloat162float(h1));
                *(__nv_bfloat162*)(g_wf_hi + obase + i * 4 + j) = hv;
                *(__nv_bfloat162*)(g_wf_lo + obase + i * 4 + j) = lv;
            }
        }
    }
}

// ---------------------------------------------------------------------------
// Temporal attention: heads 6..11, groups of 16 rows. Writes g_wf directly.
// ---------------------------------------------------------------------------
__global__ __launch_bounds__(128) void attn_temporal_k()
{
    int tid = blockIdx.x * 128 + threadIdx.x;
    const int TOT = Bdim * 6 * Ndim;
    if (tid >= TOT) return;
    int b = tid / (6 * Ndim);
    int rr = tid - b * (6 * Ndim);
    int h = 6 + rr / Ndim;
    int n = rr % Ndim;
    int n0 = n & ~15;
    size_t row = (((size_t)(b * Hh + h)) * Ndim + n) * HD;
    size_t gb  = (((size_t)(b * Hh + h)) * Ndim + n0) * HD;

    float4 q4[16];
    const float4* qp = (const float4*)(g_q + row);
#pragma unroll
    for (int i = 0; i < 16; i++) q4[i] = qp[i];

    float s[16];
    float mx = -1e30f;
#pragma unroll
    for (int f = 0; f < 16; f++) {
        const float4* kp = (const float4*)(g_k + gb + (size_t)f * HD);
        float a = 0.f;
#pragma unroll
        for (int i = 0; i < 16; i++) {
            float4 kv = kp[i];
            a = fmaf(q4[i].x, kv.x, a);
            a = fmaf(q4[i].y, kv.y, a);
            a = fmaf(q4[i].z, kv.z, a);
            a = fmaf(q4[i].w, kv.w, a);
        }
        s[f] = a * 0.125f;
        mx = fmaxf(mx, s[f]);
    }
    float lsum = 0.f;
#pragma unroll
    for (int f = 0; f < 16; f++) { s[f] = __expf(s[f] - mx); lsum += s[f]; }
    float inv = 1.f / lsum;
#pragma unroll
    for (int f = 0; f < 16; f++) s[f] *= inv;

    const size_t obase = ((size_t)b * Ndim + n) * Ddim + h * HD;
#pragma unroll
    for (int ch = 0; ch < 4; ch++) {
        float4 a4[4];
#pragma unroll
        for (int i = 0; i < 4; i++) a4[i] = make_float4(0.f, 0.f, 0.f, 0.f);
#pragma unroll
        for (int f = 0; f < 16; f++) {
            float p = s[f];
            const float4* vp = (const float4*)(g_v + gb + (size_t)f * HD + ch * 16);
#pragma unroll
            for (int i = 0; i < 4; i++) {
                float4 vv = vp[i];
                a4[i].x = fmaf(p, vv.x, a4[i].x);
                a4[i].y = fmaf(p, vv.y, a4[i].y);
                a4[i].z = fmaf(p, vv.z, a4[i].z);
                a4[i].w = fmaf(p, vv.w, a4[i].w);
            }
        }
#pragma unroll
        for (int i = 0; i < 4; i++) {
            float vals[4] = { a4[i].x, a4[i].y, a4[i].z, a4[i].w };
#pragma unroll
            for (int j = 0; j < 4; j += 2) {
                float v0 = vals[j], v1 = vals[j + 1];
                __nv_bfloat16 h0 = __float2bfloat16(v0);
                __nv_bfloat16 h1 = __float2bfloat16(v1);
                __nv_bfloat162 hv; hv.x = h0; hv.y = h1;
                __nv_bfloat162 lv;
                lv.x = __float2bfloat16(v0 - __bfloat162float(h0));
                lv.y = __float2bfloat16(v1 - __bfloat162float(h1));
                size_t o = obase + ch * 16 + i * 4 + j;
                *(__nv_bfloat162*)(g_wf_hi + o) = hv;
                *(__nv_bfloat162*)(g_wf_lo + o) = lv;
            }
        }
    }
}

// ---------------------------------------------------------------------------
// Launch
// ---------------------------------------------------------------------------
extern "C" void kernel_launch(void* const* d_in, const int* in_sizes, int n_in,
                              void* d_out, int out_size)
{
    const float* x      = (const float*)d_in[0];
    const float* w_qkv  = (const float*)d_in[1];
    const float* w_proj = (const float*)d_in[2];
    const float* b_proj = (const float*)d_in[3];
    float* out = (float*)d_out;

    float *p_q, *p_k, *p_v;
    __nv_bfloat16 *p_xhi, *p_xlo, *p_qkvw_hi, *p_qkvw_lo;
    __nv_bfloat16 *p_projw_hi, *p_projw_lo, *p_wfhi, *p_wflo;
    cudaGetSymbolAddress((void**)&p_q, g_q);
    cudaGetSymbolAddress((void**)&p_k, g_k);
    cudaGetSymbolAddress((void**)&p_v, g_v);
    cudaGetSymbolAddress((void**)&p_xhi, g_xhi);
    cudaGetSymbolAddress((void**)&p_xlo, g_xlo);
    cudaGetSymbolAddress((void**)&p_qkvw_hi, g_wqkv_hi);
    cudaGetSymbolAddress((void**)&p_qkvw_lo, g_wqkv_lo);
    cudaGetSymbolAddress((void**)&p_projw_hi, g_wproj_hi);
    cudaGetSymbolAddress((void**)&p_projw_lo, g_wproj_lo);
    cudaGetSymbolAddress((void**)&p_wfhi, g_wf_hi);
    cudaGetSymbolAddress((void**)&p_wflo, g_wf_lo);

    cudaFuncSetAttribute(tgemm_k, cudaFuncAttributeMaxDynamicSharedMemorySize, GSMEM);

    // 0) bf16 splits of inputs / weights
    cvt_split_k<<<(unsigned)((MD_ELEMS + 255) / 256), 256>>>(x, p_xhi, p_xlo, MD_ELEMS);
    cvt_split_k<<<(unsigned)(((size_t)E3 * Ddim + 255) / 256), 256>>>(
        w_qkv, p_qkvw_hi, p_qkvw_lo, (size_t)E3 * Ddim);
    cvt_split_k<<<(unsigned)(((size_t)Ddim * Ddim + 255) / 256), 256>>>(
        w_proj, p_projw_hi, p_projw_lo, (size_t)Ddim * Ddim);

    // 1) qkv GEMM with fused scatter into q/k/v head layout
    tgemm_k<<<dim3(E3 / 128, Mrows / 128), 256, GSMEM>>>(
        p_xhi, p_xlo, p_qkvw_hi, p_qkvw_lo, nullptr, nullptr, E3, 0,
        p_q, p_k, p_v);

    // 2) spatial attention (writes g_wf_hi/lo directly)
    attn_spatial_k<<<768, SPAT_T>>>();

    // 3) temporal attention (writes g_wf_hi/lo directly)
    attn_temporal_k<<<(Bdim * 6 * Ndim) / 128, 128>>>();

    // 4) out = wf @ w_proj^T + b_proj
    tgemm_k<<<dim3(Ddim / 128, Mrows / 128), 256, GSMEM>>>(
        p_wfhi, p_wflo, p_projw_hi, p_projw_lo, b_proj, out, Ddim, 1,
        nullptr, nullptr, nullptr);
}